// round 9
// baseline (speedup 1.0000x reference)
#include <cuda_runtime.h>
#include <cstdint>

// Problem constants
#define NTOT 8192            // B*N patch tiles
#define TPC  16              // tiles per CTA
#define GRID (NTOT / TPC)    // 512
#define INV_TEMP 10.0f
#define LN_EPS 1e-5f

__device__ __forceinline__ const float4* patch_ptr(const float* __restrict__ spikes,
                                                   int g, int jp) {
    const int b = g >> 10, n = g & 1023;
    const int py = n >> 5, px = n & 31;
    return (const float4*)(spikes + ((size_t)b << 16)
                           + ((py << 3) + (jp >> 1)) * 256
                           + (px << 3) + ((jp & 1) << 2));
}

// matvec tile: FMAs + 16-lane shuffle reduce + write s_out (4 chains interleaved)
__device__ __forceinline__ void matvec_tile(const float4 w0, const float4 w1,
                                            const float4 w2, const float4 w3,
                                            const float4 p, float* __restrict__ so,
                                            int jp, int r0) {
    float a0 = w0.x * p.x + w0.y * p.y + w0.z * p.z + w0.w * p.w;
    float a1 = w1.x * p.x + w1.y * p.y + w1.z * p.z + w1.w * p.w;
    float a2 = w2.x * p.x + w2.y * p.y + w2.z * p.z + w2.w * p.w;
    float a3 = w3.x * p.x + w3.y * p.y + w3.z * p.z + w3.w * p.w;
#pragma unroll
    for (int o = 1; o < 16; o <<= 1) {
        a0 += __shfl_xor_sync(0xffffffffu, a0, o);
        a1 += __shfl_xor_sync(0xffffffffu, a1, o);
        a2 += __shfl_xor_sync(0xffffffffu, a2, o);
        a3 += __shfl_xor_sync(0xffffffffu, a3, o);
    }
    if (jp == 0) {
        so[r0]      = a0;
        so[r0 + 16] = a1;
        so[r0 + 32] = a2;
        so[r0 + 48] = a3;
    }
}

// warp-0 epilogue: LN + softmax(/0.1) + gated affine + fold-store
__device__ __forceinline__ void epilogue(int g, const float* __restrict__ so,
                                         const float* __restrict__ spikes,
                                         float gm0, float gm1, float bt0, float bt1,
                                         const float* __restrict__ gates,
                                         const float* __restrict__ biases,
                                         float* __restrict__ out, int l) {
    const int b = g >> 10, n = g & 1023;
    const int py = n >> 5, px = n & 31;
    const int l2 = l + 32;
    const float* pb = spikes + ((size_t)b << 16) + (py << 3) * 256 + (px << 3);

    const float v0 = so[l];
    const float v1 = so[l2];
    const float q0 = __ldg(&pb[(l  >> 3) * 256 + (l  & 7)]);   // L1-hot
    const float q1 = __ldg(&pb[(l2 >> 3) * 256 + (l2 & 7)]);

    float sm = v0 + v1;
    float s2 = v0 * v0 + v1 * v1;
    float ps = q0 + q1;
#pragma unroll
    for (int o = 16; o > 0; o >>= 1) {
        sm += __shfl_xor_sync(0xffffffffu, sm, o);
        s2 += __shfl_xor_sync(0xffffffffu, s2, o);
        ps += __shfl_xor_sync(0xffffffffu, ps, o);
    }
    const float mu   = sm * (1.0f / 64.0f);
    const float rstd = rsqrtf(s2 * (1.0f / 64.0f) - mu * mu + LN_EPS);

    const float z0 = ((v0 - mu) * rstd * gm0 + bt0) * INV_TEMP;
    const float z1 = ((v1 - mu) * rstd * gm1 + bt1) * INV_TEMP;

    float mx = fmaxf(z0, z1);
#pragma unroll
    for (int o = 16; o > 0; o >>= 1)
        mx = fmaxf(mx, __shfl_xor_sync(0xffffffffu, mx, o));

    const float e0 = __expf(z0 - mx);
    const float e1 = __expf(z1 - mx);
    float se = e0 + e1;
#pragma unroll
    for (int o = 16; o > 0; o >>= 1)
        se += __shfl_xor_sync(0xffffffffu, se, o);

    const float scale = (__ldg(&gates[n]) * ps + __ldg(&biases[n])) / se;

    float* ob = out + ((size_t)b << 16) + (py << 3) * 256 + (px << 3);
    ob[(l  >> 3) * 256 + (l  & 7)] = e0 * scale;
    ob[(l2 >> 3) * 256 + (l2 & 7)] = e1 * scale;
}

__global__ __launch_bounds__(256)
void scs_fused(const float* __restrict__ spikes,
               const float* __restrict__ Wd,
               const float* __restrict__ gamma,
               const float* __restrict__ beta,
               const float* __restrict__ gates,
               const float* __restrict__ biases,
               float* __restrict__ out) {
    __shared__ float s_out[2][64];

    const int tid = threadIdx.x;
    const int jp  = tid & 15;
    const int r0  = tid >> 4;
    const int l   = tid & 31;
    const int start = blockIdx.x * TPC;

    const float4* Wp = (const float4*)(Wd + ((size_t)start << 12));

    float gm0 = 0.f, gm1 = 0.f, bt0 = 0.f, bt1 = 0.f;
    if (tid < 32) {
        gm0 = __ldg(&gamma[l]);  gm1 = __ldg(&gamma[l + 32]);
        bt0 = __ldg(&beta[l]);   bt1 = __ldg(&beta[l + 32]);
    }

    // prologue: tile 0 -> register set A
    float4 A0 = __ldcs(Wp + tid);
    float4 A1 = __ldcs(Wp + tid + 256);
    float4 A2 = __ldcs(Wp + tid + 512);
    float4 A3 = __ldcs(Wp + tid + 768);
    float4 PA = __ldg(patch_ptr(spikes, start, jp));

#pragma unroll 1
    for (int i = 0; i < TPC; i += 2) {
        // issue tile i+1 -> set B (in flight during tile i's compute+epilogue)
        const float4* Wn = Wp + ((size_t)(i + 1) << 10);
        float4 B0 = __ldcs(Wn + tid);
        float4 B1 = __ldcs(Wn + tid + 256);
        float4 B2 = __ldcs(Wn + tid + 512);
        float4 B3 = __ldcs(Wn + tid + 768);
        float4 PB = __ldg(patch_ptr(spikes, start + i + 1, jp));

        // ---- tile i ----
        matvec_tile(A0, A1, A2, A3, PA, s_out[0], jp, r0);
        __syncthreads();

        // issue tile i+2 -> set A (in flight during tile i epilogue + tile i+1 compute)
        if (i + 2 < TPC) {
            const float4* Wn2 = Wp + ((size_t)(i + 2) << 10);
            A0 = __ldcs(Wn2 + tid);
            A1 = __ldcs(Wn2 + tid + 256);
            A2 = __ldcs(Wn2 + tid + 512);
            A3 = __ldcs(Wn2 + tid + 768);
            PA = __ldg(patch_ptr(spikes, start + i + 2, jp));
        }
        if (tid < 32)
            epilogue(start + i, s_out[0], spikes, gm0, gm1, bt0, bt1,
                     gates, biases, out, l);

        // ---- tile i+1 ----
        matvec_tile(B0, B1, B2, B3, PB, s_out[1], jp, r0);
        __syncthreads();

        if (tid < 32)
            epilogue(start + i + 1, s_out[1], spikes, gm0, gm1, bt0, bt1,
                     gates, biases, out, l);
    }
}

extern "C" void kernel_launch(void* const* d_in, const int* in_sizes, int n_in,
                              void* d_out, int out_size) {
    const float* spikes = (const float*)d_in[0];
    const float* Wd     = (const float*)d_in[1];
    const float* gamma  = (const float*)d_in[2];
    const float* beta   = (const float*)d_in[3];
    const float* gates  = (const float*)d_in[4];
    const float* biases = (const float*)d_in[5];
    float* out = (float*)d_out;

    scs_fused<<<GRID, 256>>>(spikes, Wd, gamma, beta, gates, biases, out);
}

// round 10
// speedup vs baseline: 1.4893x; 1.4893x over previous
#include <cuda_runtime.h>
#include <cstdint>

// Problem constants
#define NTOT 8192
#define INV_TEMP 10.0f
#define LN_EPS 1e-5f

// 2 MB scratch for raw matvec results [NTOT][64]
__device__ float g_raw[NTOT * 64];

// ============ Kernel 1: pure streaming matvec (no smem, no barriers) ============
__global__ __launch_bounds__(256)
void scs_matvec(const float* __restrict__ spikes,
                const float* __restrict__ Wd) {
    const int blk = blockIdx.x;          // patch tile g = b*1024 + n
    const int tid = threadIdx.x;
    const int b   = blk >> 10;
    const int n   = blk & 1023;
    const int py  = n >> 5;
    const int px  = n & 31;

    // ---- per-warp direct patch load: lane (tid&15) gets patch float4 jp ----
    const int jp = tid & 15;
    const float4* sp = (const float4*)(spikes + ((size_t)b << 16)
                                       + ((py << 3) + (jp >> 1)) * 256
                                       + (px << 3) + ((jp & 1) << 2));
    const float4 p = __ldg(sp);

    // ---- warp-contiguous streaming W loads (512B per warp instruction) ----
    const float4* Wp = (const float4*)(Wd + ((size_t)blk << 12));
    const float4 w0 = __ldcs(Wp + tid);
    const float4 w1 = __ldcs(Wp + tid + 256);
    const float4 w2 = __ldcs(Wp + tid + 512);
    const float4 w3 = __ldcs(Wp + tid + 768);

    float a0 = w0.x * p.x + w0.y * p.y + w0.z * p.z + w0.w * p.w;
    float a1 = w1.x * p.x + w1.y * p.y + w1.z * p.z + w1.w * p.w;
    float a2 = w2.x * p.x + w2.y * p.y + w2.z * p.z + w2.w * p.w;
    float a3 = w3.x * p.x + w3.y * p.y + w3.z * p.z + w3.w * p.w;

#pragma unroll
    for (int o = 1; o < 16; o <<= 1) {
        a0 += __shfl_xor_sync(0xffffffffu, a0, o);
        a1 += __shfl_xor_sync(0xffffffffu, a1, o);
        a2 += __shfl_xor_sync(0xffffffffu, a2, o);
        a3 += __shfl_xor_sync(0xffffffffu, a3, o);
    }
    if (jp == 0) {
        const int r0 = tid >> 4;         // 0..15
        float* dst = g_raw + ((size_t)blk << 6);
        dst[r0]      = a0;
        dst[r0 + 16] = a1;
        dst[r0 + 32] = a2;
        dst[r0 + 48] = a3;
    }

    // signal dependents: our g_raw stores are done (PDL)
    asm volatile("griddepcontrol.launch_dependents;");
}

// ============ Kernel 2: LN + softmax + gated affine + fold (1 warp / patch) ============
__global__ __launch_bounds__(256)
void scs_epilogue(const float* __restrict__ spikes,
                  const float* __restrict__ gamma,
                  const float* __restrict__ beta,
                  const float* __restrict__ gates,
                  const float* __restrict__ biases,
                  float* __restrict__ out) {
    const int w   = threadIdx.x >> 5;
    const int l   = threadIdx.x & 31;
    const int g   = (blockIdx.x << 3) + w;
    const int b   = g >> 10;
    const int n   = g & 1023;
    const int py  = n >> 5;
    const int px  = n & 31;
    const int l2  = l + 32;

    // ---- pre-dependency work: everything NOT written by the primary ----
    const float gm0 = __ldg(&gamma[l]),  gm1 = __ldg(&gamma[l2]);
    const float bt0 = __ldg(&beta[l]),   bt1 = __ldg(&beta[l2]);
    const float gt  = __ldg(&gates[n]);
    const float bi  = __ldg(&biases[n]);

    const float* sb = spikes + ((size_t)b << 16) + (py << 3) * 256 + (px << 3);
    const float q0 = __ldg(&sb[(l  >> 3) * 256 + (l  & 7)]);
    const float q1 = __ldg(&sb[(l2 >> 3) * 256 + (l2 & 7)]);

    float ps = q0 + q1;
#pragma unroll
    for (int o = 16; o > 0; o >>= 1)
        ps += __shfl_xor_sync(0xffffffffu, ps, o);
    const float affine = gt * ps + bi;

    // ---- wait for primary's g_raw stores ----
    asm volatile("griddepcontrol.wait;" ::: "memory");

    const float* raw = g_raw + ((size_t)g << 6);
    const float v0 = raw[l];
    const float v1 = raw[l2];

    float sm = v0 + v1;
    float s2 = v0 * v0 + v1 * v1;
#pragma unroll
    for (int o = 16; o > 0; o >>= 1) {
        sm += __shfl_xor_sync(0xffffffffu, sm, o);
        s2 += __shfl_xor_sync(0xffffffffu, s2, o);
    }
    const float mu   = sm * (1.0f / 64.0f);
    const float rstd = rsqrtf(s2 * (1.0f / 64.0f) - mu * mu + LN_EPS);

    const float z0 = ((v0 - mu) * rstd * gm0 + bt0) * INV_TEMP;
    const float z1 = ((v1 - mu) * rstd * gm1 + bt1) * INV_TEMP;

    float mx = fmaxf(z0, z1);
#pragma unroll
    for (int o = 16; o > 0; o >>= 1)
        mx = fmaxf(mx, __shfl_xor_sync(0xffffffffu, mx, o));

    const float e0 = __expf(z0 - mx);
    const float e1 = __expf(z1 - mx);
    float se = e0 + e1;
#pragma unroll
    for (int o = 16; o > 0; o >>= 1)
        se += __shfl_xor_sync(0xffffffffu, se, o);

    const float scale = affine / se;

    float* ob = out + ((size_t)b << 16) + (py << 3) * 256 + (px << 3);
    ob[(l  >> 3) * 256 + (l  & 7)]   = e0 * scale;
    ob[(l2 >> 3) * 256 + (l2 & 7)]   = e1 * scale;
}

extern "C" void kernel_launch(void* const* d_in, const int* in_sizes, int n_in,
                              void* d_out, int out_size) {
    const float* spikes = (const float*)d_in[0];
    const float* Wd     = (const float*)d_in[1];
    const float* gamma  = (const float*)d_in[2];
    const float* beta   = (const float*)d_in[3];
    const float* gates  = (const float*)d_in[4];
    const float* biases = (const float*)d_in[5];
    float* out = (float*)d_out;

    // primary
    scs_matvec<<<NTOT, 256>>>(spikes, Wd);

    // dependent: programmatic launch (overlaps its ramp-up with primary's tail)
    cudaLaunchConfig_t cfg = {};
    cfg.gridDim  = dim3(NTOT / 8);
    cfg.blockDim = dim3(256);
    cudaLaunchAttribute attr[1];
    attr[0].id = cudaLaunchAttributeProgrammaticStreamSerialization;
    attr[0].val.programmaticStreamSerializationAllowed = 1;
    cfg.attrs = attr;
    cfg.numAttrs = 1;
    cudaLaunchKernelEx(&cfg, scs_epilogue, spikes, gamma, beta, gates, biases, out);
}